// round 15
// baseline (speedup 1.0000x reference)
#include <cuda_runtime.h>
#include <cstdint>

#define N_NODES   50000
#define N_EDGES   1600000
#define N_GRAPHS  128
#define EDGE_DIM  43
#define EDGE_PAD  44
#define IN_DIM    35
#define HDIM      128
#define CHUNK     32
#define KPAD      36
#define N_CHUNKS  (N_EDGES / CHUNK)   // 50000 exactly
static_assert(N_EDGES == N_CHUNKS * CHUNK, "edges must tile by CHUNK");

// ------------------------- scratch (device globals; no allocation) ----------
__device__ int      g_ei64;
__device__ int      g_b64;
__device__ int      g_src[N_EDGES];
__device__ int      g_batch[N_NODES];
__device__ int      g_perm[N_EDGES];
__device__ int      g_nid[N_EDGES];          // node id per sorted edge
__device__ int      g_counts[N_NODES + 1];
__device__ int      g_offs[N_NODES + 1];
__device__ int      g_cursor[N_NODES];
__device__ alignas(16) float g_eaP[(size_t)N_EDGES * EDGE_PAD];
__device__ alignas(16) float g_hA[(size_t)N_NODES * HDIM];
__device__ alignas(16) float g_hB[(size_t)N_NODES * HDIM];
__device__ alignas(16) float g_np[(size_t)N_NODES * HDIM];
__device__ float    g_gate[N_NODES];
__device__ unsigned g_gmax[N_GRAPHS];
__device__ float    g_gsum[N_GRAPHS];
__device__ int      g_glo[N_GRAPHS];
__device__ int      g_ghi[N_GRAPHS];
__device__ float    g_emb[N_GRAPHS * HDIM];

// ------------------------- helpers -----------------------------------------
// single-MUFU tanh (validated R8/R10-R13: end-to-end rel_err 1.4e-5 < 1e-3 gate)
__device__ __forceinline__ float tanh_mufu(float x) {
    float y;
    asm("tanh.approx.f32 %0, %1;" : "=f"(y) : "f"(x));
    return y;
}

__device__ __forceinline__ unsigned long long pack2(float lo, float hi) {
    unsigned long long p;
    asm("mov.b64 %0, {%1, %2};" : "=l"(p) : "f"(lo), "f"(hi));
    return p;
}
__device__ __forceinline__ void unpack2(unsigned long long p, float& lo, float& hi) {
    asm("mov.b64 {%0, %1}, %2;" : "=f"(lo), "=f"(hi) : "l"(p));
}
#define FMA2(d, a, b) \
    asm("fma.rn.f32x2 %0, %1, %2, %0;" : "+l"(d) : "l"(a), "l"(b))

__device__ __forceinline__ unsigned enc_f(float f) {
    unsigned u = __float_as_uint(f);
    return (u & 0x80000000u) ? ~u : (u | 0x80000000u);
}
__device__ __forceinline__ float dec_f(unsigned e) {
    unsigned u = (e & 0x80000000u) ? (e & 0x7fffffffu) : ~e;
    return __uint_as_float(u);
}
#define ENC_NEG_INF 0x007fffffu

// ------------------------- kernels ------------------------------------------

__global__ void k_detect(const int* __restrict__ ei32, const int* __restrict__ b32) {
    if (blockIdx.x == 0 && threadIdx.x == 0) {
        int all0 = 1;
        for (int i = 0; i < 64; i++) {
            long long j = 1LL + 2LL * ((long long)i * (N_EDGES - 1) / 63);
            if (ei32[j] != 0) { all0 = 0; break; }
        }
        g_ei64 = all0;
        all0 = 1;
        for (int i = 0; i < 64; i++) {
            long long j = 1LL + 2LL * ((long long)i * (N_NODES / 2 - 1) / 63);
            if (b32[j] != 0) { all0 = 0; break; }
        }
        g_b64 = all0;
    }
}

__global__ void k_init() {
    int i = blockIdx.x * blockDim.x + threadIdx.x;
    int stride = gridDim.x * blockDim.x;
    for (int t = i; t <= N_NODES; t += stride) g_counts[t] = 0;
    for (int t = i; t < N_GRAPHS; t += stride) {
        g_gmax[t] = ENC_NEG_INF;
        g_gsum[t] = 0.0f;
        g_glo[t]  = 0x7fffffff;
        g_ghi[t]  = -1;
    }
    for (int t = i; t < N_GRAPHS * HDIM; t += stride) g_emb[t] = 0.0f;
}

__global__ void k_hist(const int* __restrict__ ei32) {
    int e = blockIdx.x * blockDim.x + threadIdx.x;
    if (e < N_EDGES) {
        long long idx = g_ei64 ? (2LL * e) : (long long)e;
        int s = ei32[idx];
        s = min(max(s, 0), N_NODES - 1);
        g_src[e] = s;
        atomicAdd(&g_counts[s], 1);
    }
}

__global__ void k_batchload(const int* __restrict__ b32) {
    int n = blockIdx.x * blockDim.x + threadIdx.x;
    if (n < N_NODES) {
        long long idx = g_b64 ? (2LL * n) : (long long)n;
        int b = b32[idx];
        g_batch[n] = min(max(b, 0), N_GRAPHS - 1);
    }
}

#define SCAN_T 1024
#define SCAN_CH ((N_NODES + SCAN_T - 1) / SCAN_T)
__global__ void k_scan() {
    __shared__ int ssum[SCAN_T];
    int t = threadIdx.x;
    int beg = t * SCAN_CH;
    int end = min(beg + SCAN_CH, N_NODES);
    int s = 0;
    for (int i = beg; i < end; i++) s += g_counts[i];
    ssum[t] = s;
    __syncthreads();
    for (int off = 1; off < SCAN_T; off <<= 1) {
        int v = (t >= off) ? ssum[t - off] : 0;
        __syncthreads();
        ssum[t] += v;
        __syncthreads();
    }
    int run = ssum[t] - s;
    for (int i = beg; i < end; i++) {
        g_offs[i] = run;
        g_cursor[i] = run;
        run += g_counts[i];
    }
    if (t == SCAN_T - 1) g_offs[N_NODES] = run;
}

__global__ void k_scatter() {
    int e = blockIdx.x * blockDim.x + threadIdx.x;
    if (e < N_EDGES) {
        int s = g_src[e];
        int p = atomicAdd(&g_cursor[s], 1);
        g_perm[p] = e;
    }
}

__global__ void k_permute(const float* __restrict__ edge_attr) {
    int gt   = blockIdx.x * blockDim.x + threadIdx.x;
    int warp = gt >> 5;
    int lane = gt & 31;
    int nw   = (gridDim.x * blockDim.x) >> 5;
    for (int i = warp; i < N_EDGES; i += nw) {
        int e = g_perm[i];
        const float* s = edge_attr + (size_t)e * EDGE_DIM;
        float* d = g_eaP + (size_t)i * EDGE_PAD;
        d[lane] = s[lane];
        int l2 = lane + 32;
        if (l2 < EDGE_DIM) d[l2] = s[l2];
        if (l2 == EDGE_DIM) d[EDGE_DIM] = 0.0f;
        if (lane == 0) g_nid[i] = g_src[e];
    }
}

// np = Wn_x @ h + bn
__global__ __launch_bounds__(128) void k_np(
    const float* __restrict__ hin, int indim,
    const float* __restrict__ Wn, int wstride, const float* __restrict__ bn)
{
    extern __shared__ float sm[];
    float* Wn_sh = sm;                          // [k*128 + j]
    float* h_sh  = sm + indim * HDIM;           // [k*4 + node]
    float* bn_sh = h_sh + indim * 4;
    int tid = threadIdx.x;

    for (int t = tid; t < indim * HDIM; t += 128) {
        int j = t / indim, k = t % indim;
        Wn_sh[k * HDIM + j] = Wn[(size_t)j * wstride + k];
    }
    bn_sh[tid] = bn[tid];
    __syncthreads();

    for (int g = blockIdx.x * 4; g < N_NODES; g += gridDim.x * 4) {
        for (int t = tid; t < indim * 4; t += 128) {
            int node = t / indim, k = t % indim;
            int n = g + node;
            h_sh[k * 4 + node] = (n < N_NODES) ? hin[(size_t)n * indim + k] : 0.0f;
        }
        __syncthreads();
        unsigned long long a01 = 0, a23 = 0;
        #pragma unroll 4
        for (int k = 0; k < indim; k++) {
            unsigned long long wn2 = pack2(Wn_sh[k * HDIM + tid], Wn_sh[k * HDIM + tid]);
            ulonglong2 h2 = *reinterpret_cast<const ulonglong2*>(&h_sh[k * 4]);
            FMA2(a01, wn2, h2.x); FMA2(a23, wn2, h2.y);
        }
        float a0, a1, a2, a3;
        unpack2(a01, a0, a1); unpack2(a23, a2, a3);
        float bnv = bn_sh[tid];
        if (g + 0 < N_NODES) g_np[(size_t)(g+0)*HDIM+tid] = a0 + bnv;
        if (g + 1 < N_NODES) g_np[(size_t)(g+1)*HDIM+tid] = a1 + bnv;
        if (g + 2 < N_NODES) g_np[(size_t)(g+2)*HDIM+tid] = a2 + bnv;
        if (g + 3 < N_NODES) g_np[(size_t)(g+3)*HDIM+tid] = a3 + bnv;
        __syncthreads();
    }
}

// hroot = tanh(Wr @ h + br)
__global__ __launch_bounds__(128) void k_root(
    const float* __restrict__ hin, int indim,
    const float* __restrict__ Wr, const float* __restrict__ br,
    float* __restrict__ hroot)
{
    extern __shared__ float sm[];
    float* Wr_sh = sm;                          // [k*128 + j]
    float* h_sh  = sm + indim * HDIM;           // [k*4 + node]
    float* br_sh = h_sh + indim * 4;
    int tid = threadIdx.x;

    for (int t = tid; t < indim * HDIM; t += 128) {
        int j = t / indim, k = t % indim;
        Wr_sh[k * HDIM + j] = Wr[(size_t)j * indim + k];
    }
    br_sh[tid] = br[tid];
    __syncthreads();

    for (int g = blockIdx.x * 4; g < N_NODES; g += gridDim.x * 4) {
        for (int t = tid; t < indim * 4; t += 128) {
            int node = t / indim, k = t % indim;
            int n = g + node;
            h_sh[k * 4 + node] = (n < N_NODES) ? hin[(size_t)n * indim + k] : 0.0f;
        }
        __syncthreads();
        unsigned long long r01 = 0, r23 = 0;
        #pragma unroll 4
        for (int k = 0; k < indim; k++) {
            unsigned long long wr2 = pack2(Wr_sh[k * HDIM + tid], Wr_sh[k * HDIM + tid]);
            ulonglong2 h2 = *reinterpret_cast<const ulonglong2*>(&h_sh[k * 4]);
            FMA2(r01, wr2, h2.x); FMA2(r23, wr2, h2.y);
        }
        float r0, r1, r2, r3;
        unpack2(r01, r0, r1); unpack2(r23, r2, r3);
        float brv = br_sh[tid];
        if (g + 0 < N_NODES) hroot[(size_t)(g+0)*HDIM+tid] = tanh_mufu(r0 + brv);
        if (g + 1 < N_NODES) hroot[(size_t)(g+1)*HDIM+tid] = tanh_mufu(r1 + brv);
        if (g + 2 < N_NODES) hroot[(size_t)(g+2)*HDIM+tid] = tanh_mufu(r2 + brv);
        if (g + 3 < N_NODES) hroot[(size_t)(g+3)*HDIM+tid] = tanh_mufu(r3 + brv);
        __syncthreads();
    }
}

// edge-streaming fused projection + tanh + segmented reduce.
// R14: 2 cols/thread (data sharing from R13, keeps L1 low) + weights in
// SHARED hoisted to k-outer loop (kills R13's 172-reg occupancy collapse).
// Per warp per chunk: 258 LDS (86 weight + 172 data) vs R12's 344, regs ~116.
__global__ __launch_bounds__(128, 4) void k_agg(
    const float* __restrict__ Wn, int wstride, int woff,
    float* __restrict__ hout, int nck)
{
    const int tid   = threadIdx.x;
    const int lid   = tid & 63;          // column pair id
    const int ebase = (tid >> 6) * 16;   // edge offset within chunk (0 or 16)
    const int c0 = lid, c1 = lid + 64;   // owned output columns

    __shared__ float Wsh[EDGE_DIM * HDIM];                 // [k*128 + col] 22016B
    __shared__ alignas(16) float ea[2][EDGE_PAD * KPAD];   // 12672B
    __shared__ int nid_sh[2][CHUNK];

    // weight load: each thread its 2 columns (once per kernel)
    #pragma unroll 1
    for (int k = 0; k < EDGE_DIM; k++) {
        Wsh[k * HDIM + c0] = Wn[(size_t)c0 * wstride + woff + k];
        Wsh[k * HDIM + c1] = Wn[(size_t)c1 * wstride + woff + k];
    }

    const int cpb = (nck + gridDim.x - 1) / gridDim.x;
    const int c0b = blockIdx.x * cpb;
    const int c1b = min(c0b + cpb, nck);
    if (c0b >= c1b) { return; }

    // staging slots: l = tid, tid+128, tid+256 (<352); l = e*11+kk bijection
    const int e0_ = tid / 11,          kk0 = tid % 11;
    const int e1_ = (tid + 128) / 11,  kk1 = (tid + 128) % 11;
    const int e2_ = (tid + 256) / 11,  kk2 = (tid + 256) % 11;
    const bool has2 = (tid + 256) < 352;

    {   // prologue: stage chunk c0b into buffer 0
        size_t base = (size_t)c0b * CHUNK;
        float4 v0 = *reinterpret_cast<const float4*>(g_eaP + (base + e0_) * EDGE_PAD + 4 * kk0);
        float4 v1 = *reinterpret_cast<const float4*>(g_eaP + (base + e1_) * EDGE_PAD + 4 * kk1);
        float4 v2 = has2 ? *reinterpret_cast<const float4*>(g_eaP + (base + e2_) * EDGE_PAD + 4 * kk2)
                         : make_float4(0.f, 0.f, 0.f, 0.f);
        float* b = ea[0];
        b[(4*kk0+0)*KPAD + e0_] = v0.x; b[(4*kk0+1)*KPAD + e0_] = v0.y;
        b[(4*kk0+2)*KPAD + e0_] = v0.z; b[(4*kk0+3)*KPAD + e0_] = v0.w;
        b[(4*kk1+0)*KPAD + e1_] = v1.x; b[(4*kk1+1)*KPAD + e1_] = v1.y;
        b[(4*kk1+2)*KPAD + e1_] = v1.z; b[(4*kk1+3)*KPAD + e1_] = v1.w;
        if (has2) {
            b[(4*kk2+0)*KPAD + e2_] = v2.x; b[(4*kk2+1)*KPAD + e2_] = v2.y;
            b[(4*kk2+2)*KPAD + e2_] = v2.z; b[(4*kk2+3)*KPAD + e2_] = v2.w;
        }
        if (tid < CHUNK) nid_sh[0][tid] = g_nid[base + tid];
    }
    __syncthreads();

    int   cur = -1;
    float av0 = 0.0f, av1 = 0.0f;
    float np0 = 0.0f, np1 = 0.0f;

    for (int c = c0b; c < c1b; c++) {
        const int bi = (c - c0b) & 1;      // local parity (prologue filled buf 0)
        const bool more = (c + 1) < c1b;

        float4 v0, v1, v2;
        int nxt_nid = 0;
        if (more) {
            size_t base = (size_t)(c + 1) * CHUNK;
            v0 = *reinterpret_cast<const float4*>(g_eaP + (base + e0_) * EDGE_PAD + 4 * kk0);
            v1 = *reinterpret_cast<const float4*>(g_eaP + (base + e1_) * EDGE_PAD + 4 * kk1);
            if (has2)
                v2 = *reinterpret_cast<const float4*>(g_eaP + (base + e2_) * EDGE_PAD + 4 * kk2);
            if (tid < CHUNK) nxt_nid = g_nid[base + tid];
        }

        // compute: 16 edges (this thread's group) x 2 columns, k-outer
        const float* bp = ea[bi] + ebase;
        unsigned long long aA[8] = {0,0,0,0,0,0,0,0};
        unsigned long long aB[8] = {0,0,0,0,0,0,0,0};
        #pragma unroll
        for (int k = 0; k < EDGE_DIM; k++) {
            float wa = Wsh[k * HDIM + c0];
            float wb = Wsh[k * HDIM + c1];
            unsigned long long wA = pack2(wa, wa);
            unsigned long long wB = pack2(wb, wb);
            const float* row = bp + k * KPAD;
            ulonglong2 q0 = *reinterpret_cast<const ulonglong2*>(row);
            ulonglong2 q1 = *reinterpret_cast<const ulonglong2*>(row + 4);
            ulonglong2 q2 = *reinterpret_cast<const ulonglong2*>(row + 8);
            ulonglong2 q3 = *reinterpret_cast<const ulonglong2*>(row + 12);
            FMA2(aA[0], wA, q0.x); FMA2(aA[1], wA, q0.y);
            FMA2(aA[2], wA, q1.x); FMA2(aA[3], wA, q1.y);
            FMA2(aA[4], wA, q2.x); FMA2(aA[5], wA, q2.y);
            FMA2(aA[6], wA, q3.x); FMA2(aA[7], wA, q3.y);
            FMA2(aB[0], wB, q0.x); FMA2(aB[1], wB, q0.y);
            FMA2(aB[2], wB, q1.x); FMA2(aB[3], wB, q1.y);
            FMA2(aB[4], wB, q2.x); FMA2(aB[5], wB, q2.y);
            FMA2(aB[6], wB, q3.x); FMA2(aB[7], wB, q3.y);
        }
        float fA[16], fB[16];
        #pragma unroll
        for (int q = 0; q < 8; q++) {
            unpack2(aA[q], fA[2*q], fA[2*q+1]);
            unpack2(aB[q], fB[2*q], fB[2*q+1]);
        }
        // segmented flush over this thread's 16 sorted edges
        #pragma unroll
        for (int p = 0; p < 16; p++) {
            int nid = nid_sh[bi][ebase + p];
            if (nid != cur) {
                float n0 = g_np[(size_t)nid * HDIM + c0];
                float n1 = g_np[(size_t)nid * HDIM + c1];
                if (cur >= 0) {
                    atomicAdd(&hout[(size_t)cur * HDIM + c0], av0);
                    atomicAdd(&hout[(size_t)cur * HDIM + c1], av1);
                }
                cur = nid; av0 = 0.0f; av1 = 0.0f; np0 = n0; np1 = n1;
            }
            av0 += tanh_mufu(np0 + fA[p]);
            av1 += tanh_mufu(np1 + fB[p]);
        }
        __syncthreads();

        if (more) {
            float* b = ea[bi ^ 1];
            b[(4*kk0+0)*KPAD + e0_] = v0.x; b[(4*kk0+1)*KPAD + e0_] = v0.y;
            b[(4*kk0+2)*KPAD + e0_] = v0.z; b[(4*kk0+3)*KPAD + e0_] = v0.w;
            b[(4*kk1+0)*KPAD + e1_] = v1.x; b[(4*kk1+1)*KPAD + e1_] = v1.y;
            b[(4*kk1+2)*KPAD + e1_] = v1.z; b[(4*kk1+3)*KPAD + e1_] = v1.w;
            if (has2) {
                b[(4*kk2+0)*KPAD + e2_] = v2.x; b[(4*kk2+1)*KPAD + e2_] = v2.y;
                b[(4*kk2+2)*KPAD + e2_] = v2.z; b[(4*kk2+3)*KPAD + e2_] = v2.w;
            }
            if (tid < CHUNK) nid_sh[bi ^ 1][tid] = nxt_nid;
            __syncthreads();
        }
    }
    if (cur >= 0) {
        atomicAdd(&hout[(size_t)cur * HDIM + c0], av0);
        atomicAdd(&hout[(size_t)cur * HDIM + c1], av1);
    }
}

// gate MLP: 128->64->32->1
__global__ __launch_bounds__(128) void k_gate(
    const float* __restrict__ h,
    const float* __restrict__ Wg1, const float* __restrict__ bg1,
    const float* __restrict__ Wg2, const float* __restrict__ bg2,
    const float* __restrict__ Wg3, const float* __restrict__ bg3)
{
    __shared__ float W1s[128 * 64];
    __shared__ float W2s[64 * 32];
    __shared__ float W3s[32];
    __shared__ float b1s[64], b2s[32];
    __shared__ float h_sh[128 * 2];
    __shared__ float g1s[64 * 2];
    int tid = threadIdx.x;

    for (int t = tid; t < 128 * 64; t += 128) {
        int j = t / 128, k = t % 128;
        W1s[k * 64 + j] = Wg1[j * 128 + k];
    }
    for (int t = tid; t < 64 * 32; t += 128) {
        int j = t / 64, k = t % 64;
        W2s[k * 32 + j] = Wg2[j * 64 + k];
    }
    if (tid < 32) W3s[tid] = Wg3[tid];
    if (tid < 64) b1s[tid] = bg1[tid];
    if (tid < 32) b2s[tid] = bg2[tid];
    __syncthreads();

    int npairs = (N_NODES + 1) / 2;
    for (int p = blockIdx.x; p < npairs; p += gridDim.x) {
        for (int t = tid; t < 256; t += 128) {
            int node = t / 128, k = t % 128;
            int n = 2 * p + node;
            h_sh[k * 2 + node] = (n < N_NODES) ? h[(size_t)n * HDIM + k] : 0.0f;
        }
        __syncthreads();
        int j = tid & 63, half = tid >> 6;
        float a = 0;
        #pragma unroll 4
        for (int k = 0; k < 128; k++) a += W1s[k * 64 + j] * h_sh[k * 2 + half];
        g1s[j * 2 + half] = fmaxf(a + b1s[j], 0.0f);
        __syncthreads();
        if (j < 32) {
            float a2 = 0;
            #pragma unroll 4
            for (int k = 0; k < 64; k++) a2 += W2s[k * 32 + j] * g1s[k * 2 + half];
            float g2 = fmaxf(a2 + b2s[j], 0.0f);
            float v = g2 * W3s[j];
            for (int o = 16; o > 0; o >>= 1) v += __shfl_down_sync(0xffffffffu, v, o);
            int n = 2 * p + half;
            if (j == 0 && n < N_NODES) g_gate[n] = v + bg3[0];
        }
        __syncthreads();
    }
}

__global__ void k_gstats() {
    int n = blockIdx.x * blockDim.x + threadIdx.x;
    if (n < N_NODES) {
        int b = g_batch[n];
        atomicMax(&g_gmax[b], enc_f(g_gate[n]));
        atomicMin(&g_glo[b], n);
        atomicMax(&g_ghi[b], n);
    }
}

__global__ void k_gsum() {
    int n = blockIdx.x * blockDim.x + threadIdx.x;
    if (n < N_NODES) {
        int b = g_batch[n];
        atomicAdd(&g_gsum[b], __expf(g_gate[n] - dec_f(g_gmax[b])));
    }
}

__global__ void k_att(float* __restrict__ att) {
    int n = blockIdx.x * blockDim.x + threadIdx.x;
    if (n < N_NODES) {
        int b = g_batch[n];
        float g = __expf(g_gate[n] - dec_f(g_gmax[b]));
        att[n] = g / (g_gsum[b] + 1e-16f);
    }
}

__global__ void k_emb(const float* __restrict__ h, const float* __restrict__ att) {
    int b = blockIdx.x, q = blockIdx.y, j = threadIdx.x;
    int lo = g_glo[b], hi = g_ghi[b];
    if (hi < lo) return;
    int len = hi - lo + 1;
    int per = (len + 3) / 4;
    int s = lo + q * per;
    int e = min(s + per, hi + 1);
    if (s >= e) return;
    float acc = 0.0f;
    for (int n = s; n < e; n++)
        acc += att[n] * h[(size_t)n * HDIM + j];
    atomicAdd(&g_emb[b * HDIM + j], acc);
}

__global__ __launch_bounds__(256) void k_final(
    const float* __restrict__ us, const float* __restrict__ ud,
    const float* __restrict__ Wl1, const float* __restrict__ bl1,
    const float* __restrict__ Wl2, const float* __restrict__ bl2,
    const float* __restrict__ Wl3, const float* __restrict__ bl3,
    const float* __restrict__ Wl,  const float* __restrict__ bl,
    float* __restrict__ outp)
{
    __shared__ float e2[256], o1[256], o2[128], o3[64], o4[4];
    int b = blockIdx.x, t = threadIdx.x;
    if (t < 128)       e2[t] = g_emb[b * 128 + t];
    else if (t < 192)  e2[t] = us[b * 64 + (t - 128)];
    else               e2[t] = ud[b * 64 + (t - 192)];
    __syncthreads();
    float a = 0;
    for (int k = 0; k < 256; k++) a += Wl1[t * 256 + k] * e2[k];
    o1[t] = fmaxf(a + bl1[t], 0.0f);
    __syncthreads();
    if (t < 128) {
        a = 0;
        for (int k = 0; k < 256; k++) a += Wl2[t * 256 + k] * o1[k];
        o2[t] = fmaxf(a + bl2[t], 0.0f);
    }
    __syncthreads();
    if (t < 64) {
        a = 0;
        for (int k = 0; k < 128; k++) a += Wl3[t * 128 + k] * o2[k];
        o3[t] = fmaxf(a + bl3[t], 0.0f);
    }
    __syncthreads();
    if (t < 4) {
        a = 0;
        for (int k = 0; k < 64; k++) a += Wl[t * 64 + k] * o3[k];
        o4[t] = a + bl[t];
    }
    __syncthreads();
    if (t == 0) {
        float s = o4[0] + o4[1] + o4[2] + o4[3];
        outp[b * 5 + 0] = o4[0];
        outp[b * 5 + 1] = o4[1];
        outp[b * 5 + 2] = o4[2];
        outp[b * 5 + 3] = o4[3];
        outp[b * 5 + 4] = s;
    }
}

// ------------------------- launch -------------------------------------------
extern "C" void kernel_launch(void* const* d_in, const int* in_sizes, int n_in,
                              void* d_out, int out_size)
{
    const float* x    = (const float*)d_in[0];
    const float* ea   = (const float*)d_in[1];
    const float* us   = (const float*)d_in[2];
    const float* ud   = (const float*)d_in[3];
    const float* W1n  = (const float*)d_in[4];
    const float* b1n  = (const float*)d_in[5];
    const float* W1r  = (const float*)d_in[6];
    const float* b1r  = (const float*)d_in[7];
    const float* W2n  = (const float*)d_in[8];
    const float* b2n  = (const float*)d_in[9];
    const float* W2r  = (const float*)d_in[10];
    const float* b2r  = (const float*)d_in[11];
    const float* W3n  = (const float*)d_in[12];
    const float* b3n  = (const float*)d_in[13];
    const float* W3r  = (const float*)d_in[14];
    const float* b3r  = (const float*)d_in[15];
    const float* Wg1  = (const float*)d_in[16];
    const float* bg1  = (const float*)d_in[17];
    const float* Wg2  = (const float*)d_in[18];
    const float* bg2  = (const float*)d_in[19];
    const float* Wg3  = (const float*)d_in[20];
    const float* bg3  = (const float*)d_in[21];
    const float* Wl1  = (const float*)d_in[22];
    const float* bl1  = (const float*)d_in[23];
    const float* Wl2  = (const float*)d_in[24];
    const float* bl2  = (const float*)d_in[25];
    const float* Wl3  = (const float*)d_in[26];
    const float* bl3  = (const float*)d_in[27];
    const float* Wl   = (const float*)d_in[28];
    const float* bl   = (const float*)d_in[29];
    const int* ei32   = (const int*)d_in[30];
    const int* b32    = (const int*)d_in[31];

    float* outp = (float*)d_out;
    float* att  = outp + N_GRAPHS * 5;

    cudaFuncSetAttribute(k_np,
                         cudaFuncAttributeMaxDynamicSharedMemorySize, 100000);
    cudaFuncSetAttribute(k_root,
                         cudaFuncAttributeMaxDynamicSharedMemorySize, 100000);

    int smemN35  = (IN_DIM * HDIM + IN_DIM * 4 + HDIM) * sizeof(float);
    int smemN128 = (HDIM * HDIM + HDIM * 4 + HDIM) * sizeof(float);

    k_detect<<<1, 32>>>(ei32, b32);                      // launch 1
    k_init<<<256, 256>>>();                              // launch 2
    k_hist<<<(N_EDGES + 255) / 256, 256>>>(ei32);        // launch 3

    // PROFILING PROBE (launch 4 == ncu slot): new k_agg on 9.5% chunk subset
    // into g_hB (fully overwritten by layer-2 k_root before any read).
    k_agg<<<1184, 128>>>(W1n, IN_DIM + EDGE_DIM, IN_DIM, g_hB, 4736);

    k_batchload<<<(N_NODES + 255) / 256, 256>>>(b32);
    k_scan<<<1, SCAN_T>>>();
    k_scatter<<<(N_EDGES + 255) / 256, 256>>>();
    k_permute<<<2048, 256>>>(ea);

    // layer 1: x(35) -> hA
    k_np<<<1184, 128, smemN35>>>(x, IN_DIM, W1n, IN_DIM + EDGE_DIM, b1n);
    k_root<<<1184, 128, smemN35>>>(x, IN_DIM, W1r, b1r, g_hA);
    k_agg<<<1184, 128>>>(W1n, IN_DIM + EDGE_DIM, IN_DIM, g_hA, N_CHUNKS);
    // layer 2: hA(128) -> hB
    k_np<<<1184, 128, smemN128>>>(g_hA, HDIM, W2n, HDIM + EDGE_DIM, b2n);
    k_root<<<1184, 128, smemN128>>>(g_hA, HDIM, W2r, b2r, g_hB);
    k_agg<<<1184, 128>>>(W2n, HDIM + EDGE_DIM, HDIM, g_hB, N_CHUNKS);
    // layer 3: hB(128) -> hA
    k_np<<<1184, 128, smemN128>>>(g_hB, HDIM, W3n, HDIM + EDGE_DIM, b3n);
    k_root<<<1184, 128, smemN128>>>(g_hB, HDIM, W3r, b3r, g_hA);
    k_agg<<<1184, 128>>>(W3n, HDIM + EDGE_DIM, HDIM, g_hA, N_CHUNKS);

    // readout
    k_gate<<<1184, 128>>>(g_hA, Wg1, bg1, Wg2, bg2, Wg3, bg3);
    k_gstats<<<(N_NODES + 255) / 256, 256>>>();
    k_gsum<<<(N_NODES + 255) / 256, 256>>>();
    k_att<<<(N_NODES + 255) / 256, 256>>>(att);
    k_emb<<<dim3(N_GRAPHS, 4), HDIM>>>(g_hA, att);
    k_final<<<N_GRAPHS, 256>>>(us, ud, Wl1, bl1, Wl2, bl2, Wl3, bl3, Wl, bl, outp);
}

// round 17
// speedup vs baseline: 1.4931x; 1.4931x over previous
#include <cuda_runtime.h>
#include <cstdint>

#define N_NODES   50000
#define N_EDGES   1600000
#define N_GRAPHS  128
#define EDGE_DIM  43
#define EDGE_PAD  44
#define IN_DIM    35
#define HDIM      128
#define CHUNK     32
#define KPAD      36
#define N_CHUNKS  (N_EDGES / CHUNK)   // 50000 exactly
static_assert(N_EDGES == N_CHUNKS * CHUNK, "edges must tile by CHUNK");

// ------------------------- scratch (device globals; no allocation) ----------
__device__ int      g_ei64;
__device__ int      g_b64;
__device__ int      g_src[N_EDGES];
__device__ int      g_batch[N_NODES];
__device__ int      g_perm[N_EDGES];
__device__ int      g_nid[N_EDGES];          // node id per sorted edge
__device__ int      g_counts[N_NODES + 1];
__device__ int      g_offs[N_NODES + 1];
__device__ int      g_cursor[N_NODES];
__device__ alignas(16) float g_eaP[(size_t)N_EDGES * EDGE_PAD];
__device__ alignas(16) float g_hA[(size_t)N_NODES * HDIM];
__device__ alignas(16) float g_hB[(size_t)N_NODES * HDIM];
__device__ alignas(16) float g_np[(size_t)N_NODES * HDIM];
__device__ float    g_gate[N_NODES];
__device__ unsigned g_gmax[N_GRAPHS];
__device__ float    g_gsum[N_GRAPHS];
__device__ int      g_glo[N_GRAPHS];
__device__ int      g_ghi[N_GRAPHS];
__device__ float    g_emb[N_GRAPHS * HDIM];

// ------------------------- helpers -----------------------------------------
// single-MUFU tanh (validated R8/R10-R15: end-to-end rel_err 1.4e-5 < 1e-3 gate)
__device__ __forceinline__ float tanh_mufu(float x) {
    float y;
    asm("tanh.approx.f32 %0, %1;" : "=f"(y) : "f"(x));
    return y;
}

__device__ __forceinline__ unsigned long long pack2(float lo, float hi) {
    unsigned long long p;
    asm("mov.b64 %0, {%1, %2};" : "=l"(p) : "f"(lo), "f"(hi));
    return p;
}
__device__ __forceinline__ void unpack2(unsigned long long p, float& lo, float& hi) {
    asm("mov.b64 {%0, %1}, %2;" : "=f"(lo), "=f"(hi) : "l"(p));
}
#define FMA2(d, a, b) \
    asm("fma.rn.f32x2 %0, %1, %2, %0;" : "+l"(d) : "l"(a), "l"(b))

__device__ __forceinline__ unsigned enc_f(float f) {
    unsigned u = __float_as_uint(f);
    return (u & 0x80000000u) ? ~u : (u | 0x80000000u);
}
__device__ __forceinline__ float dec_f(unsigned e) {
    unsigned u = (e & 0x80000000u) ? (e & 0x7fffffffu) : ~e;
    return __uint_as_float(u);
}
#define ENC_NEG_INF 0x007fffffu

// ------------------------- kernels ------------------------------------------

__global__ void k_detect(const int* __restrict__ ei32, const int* __restrict__ b32) {
    if (blockIdx.x == 0 && threadIdx.x == 0) {
        int all0 = 1;
        for (int i = 0; i < 64; i++) {
            long long j = 1LL + 2LL * ((long long)i * (N_EDGES - 1) / 63);
            if (ei32[j] != 0) { all0 = 0; break; }
        }
        g_ei64 = all0;
        all0 = 1;
        for (int i = 0; i < 64; i++) {
            long long j = 1LL + 2LL * ((long long)i * (N_NODES / 2 - 1) / 63);
            if (b32[j] != 0) { all0 = 0; break; }
        }
        g_b64 = all0;
    }
}

__global__ void k_init() {
    int i = blockIdx.x * blockDim.x + threadIdx.x;
    int stride = gridDim.x * blockDim.x;
    for (int t = i; t <= N_NODES; t += stride) g_counts[t] = 0;
    for (int t = i; t < N_GRAPHS; t += stride) {
        g_gmax[t] = ENC_NEG_INF;
        g_gsum[t] = 0.0f;
        g_glo[t]  = 0x7fffffff;
        g_ghi[t]  = -1;
    }
    for (int t = i; t < N_GRAPHS * HDIM; t += stride) g_emb[t] = 0.0f;
}

__global__ void k_hist(const int* __restrict__ ei32) {
    int e = blockIdx.x * blockDim.x + threadIdx.x;
    if (e < N_EDGES) {
        long long idx = g_ei64 ? (2LL * e) : (long long)e;
        int s = ei32[idx];
        s = min(max(s, 0), N_NODES - 1);
        g_src[e] = s;
        atomicAdd(&g_counts[s], 1);
    }
}

__global__ void k_batchload(const int* __restrict__ b32) {
    int n = blockIdx.x * blockDim.x + threadIdx.x;
    if (n < N_NODES) {
        long long idx = g_b64 ? (2LL * n) : (long long)n;
        int b = b32[idx];
        g_batch[n] = min(max(b, 0), N_GRAPHS - 1);
    }
}

#define SCAN_T 1024
#define SCAN_CH ((N_NODES + SCAN_T - 1) / SCAN_T)
__global__ void k_scan() {
    __shared__ int ssum[SCAN_T];
    int t = threadIdx.x;
    int beg = t * SCAN_CH;
    int end = min(beg + SCAN_CH, N_NODES);
    int s = 0;
    for (int i = beg; i < end; i++) s += g_counts[i];
    ssum[t] = s;
    __syncthreads();
    for (int off = 1; off < SCAN_T; off <<= 1) {
        int v = (t >= off) ? ssum[t - off] : 0;
        __syncthreads();
        ssum[t] += v;
        __syncthreads();
    }
    int run = ssum[t] - s;
    for (int i = beg; i < end; i++) {
        g_offs[i] = run;
        g_cursor[i] = run;
        run += g_counts[i];
    }
    if (t == SCAN_T - 1) g_offs[N_NODES] = run;
}

__global__ void k_scatter() {
    int e = blockIdx.x * blockDim.x + threadIdx.x;
    if (e < N_EDGES) {
        int s = g_src[e];
        int p = atomicAdd(&g_cursor[s], 1);
        g_perm[p] = e;
    }
}

__global__ void k_permute(const float* __restrict__ edge_attr) {
    int gt   = blockIdx.x * blockDim.x + threadIdx.x;
    int warp = gt >> 5;
    int lane = gt & 31;
    int nw   = (gridDim.x * blockDim.x) >> 5;
    for (int i = warp; i < N_EDGES; i += nw) {
        int e = g_perm[i];
        const float* s = edge_attr + (size_t)e * EDGE_DIM;
        float* d = g_eaP + (size_t)i * EDGE_PAD;
        d[lane] = s[lane];
        int l2 = lane + 32;
        if (l2 < EDGE_DIM) d[l2] = s[l2];
        if (l2 == EDGE_DIM) d[EDGE_DIM] = 0.0f;
        if (lane == 0) g_nid[i] = g_src[e];
    }
}

// np = Wn_x @ h + bn
__global__ __launch_bounds__(128) void k_np(
    const float* __restrict__ hin, int indim,
    const float* __restrict__ Wn, int wstride, const float* __restrict__ bn)
{
    extern __shared__ float sm[];
    float* Wn_sh = sm;                          // [k*128 + j]
    float* h_sh  = sm + indim * HDIM;           // [k*4 + node]
    float* bn_sh = h_sh + indim * 4;
    int tid = threadIdx.x;

    for (int t = tid; t < indim * HDIM; t += 128) {
        int j = t / indim, k = t % indim;
        Wn_sh[k * HDIM + j] = Wn[(size_t)j * wstride + k];
    }
    bn_sh[tid] = bn[tid];
    __syncthreads();

    for (int g = blockIdx.x * 4; g < N_NODES; g += gridDim.x * 4) {
        for (int t = tid; t < indim * 4; t += 128) {
            int node = t / indim, k = t % indim;
            int n = g + node;
            h_sh[k * 4 + node] = (n < N_NODES) ? hin[(size_t)n * indim + k] : 0.0f;
        }
        __syncthreads();
        unsigned long long a01 = 0, a23 = 0;
        #pragma unroll 4
        for (int k = 0; k < indim; k++) {
            unsigned long long wn2 = pack2(Wn_sh[k * HDIM + tid], Wn_sh[k * HDIM + tid]);
            ulonglong2 h2 = *reinterpret_cast<const ulonglong2*>(&h_sh[k * 4]);
            FMA2(a01, wn2, h2.x); FMA2(a23, wn2, h2.y);
        }
        float a0, a1, a2, a3;
        unpack2(a01, a0, a1); unpack2(a23, a2, a3);
        float bnv = bn_sh[tid];
        if (g + 0 < N_NODES) g_np[(size_t)(g+0)*HDIM+tid] = a0 + bnv;
        if (g + 1 < N_NODES) g_np[(size_t)(g+1)*HDIM+tid] = a1 + bnv;
        if (g + 2 < N_NODES) g_np[(size_t)(g+2)*HDIM+tid] = a2 + bnv;
        if (g + 3 < N_NODES) g_np[(size_t)(g+3)*HDIM+tid] = a3 + bnv;
        __syncthreads();
    }
}

// hroot = tanh(Wr @ h + br)
__global__ __launch_bounds__(128) void k_root(
    const float* __restrict__ hin, int indim,
    const float* __restrict__ Wr, const float* __restrict__ br,
    float* __restrict__ hroot)
{
    extern __shared__ float sm[];
    float* Wr_sh = sm;                          // [k*128 + j]
    float* h_sh  = sm + indim * HDIM;           // [k*4 + node]
    float* br_sh = h_sh + indim * 4;
    int tid = threadIdx.x;

    for (int t = tid; t < indim * HDIM; t += 128) {
        int j = t / indim, k = t % indim;
        Wr_sh[k * HDIM + j] = Wr[(size_t)j * indim + k];
    }
    br_sh[tid] = br[tid];
    __syncthreads();

    for (int g = blockIdx.x * 4; g < N_NODES; g += gridDim.x * 4) {
        for (int t = tid; t < indim * 4; t += 128) {
            int node = t / indim, k = t % indim;
            int n = g + node;
            h_sh[k * 4 + node] = (n < N_NODES) ? hin[(size_t)n * indim + k] : 0.0f;
        }
        __syncthreads();
        unsigned long long r01 = 0, r23 = 0;
        #pragma unroll 4
        for (int k = 0; k < indim; k++) {
            unsigned long long wr2 = pack2(Wr_sh[k * HDIM + tid], Wr_sh[k * HDIM + tid]);
            ulonglong2 h2 = *reinterpret_cast<const ulonglong2*>(&h_sh[k * 4]);
            FMA2(r01, wr2, h2.x); FMA2(r23, wr2, h2.y);
        }
        float r0, r1, r2, r3;
        unpack2(r01, r0, r1); unpack2(r23, r2, r3);
        float brv = br_sh[tid];
        if (g + 0 < N_NODES) hroot[(size_t)(g+0)*HDIM+tid] = tanh_mufu(r0 + brv);
        if (g + 1 < N_NODES) hroot[(size_t)(g+1)*HDIM+tid] = tanh_mufu(r1 + brv);
        if (g + 2 < N_NODES) hroot[(size_t)(g+2)*HDIM+tid] = tanh_mufu(r2 + brv);
        if (g + 3 < N_NODES) hroot[(size_t)(g+3)*HDIM+tid] = tanh_mufu(r3 + brv);
        __syncthreads();
    }
}

// edge-streaming fused projection + tanh + segmented reduce.
// R16: R13 structure (2 cols/thread, 16-edge groups — proven correct, L1 39%)
// with SPLIT weight store: Wa (col lid) in regs, Wb (col lid+64) in a 43x64
// shared table read once per k per sub. Cuts regs 172 -> ~128 so 4 blocks/SM.
__global__ __launch_bounds__(128, 4) void k_agg(
    const float* __restrict__ Wn, int wstride, int woff,
    float* __restrict__ hout, int nck)
{
    const int tid   = threadIdx.x;
    const int lid   = tid & 63;          // column pair id
    const int ebase = (tid >> 6) * 16;   // edge offset within chunk (0 or 16)
    const int c0 = lid, c1 = lid + 64;   // owned output columns

    float Wa[EDGE_DIM];                  // col c0 weights in regs (43)
    #pragma unroll
    for (int k = 0; k < EDGE_DIM; k++)
        Wa[k] = Wn[(size_t)c0 * wstride + woff + k];

    __shared__ float WshB[EDGE_DIM * 64];                  // [k*64 + lid] 11008B
    __shared__ alignas(16) float ea[2][EDGE_PAD * KPAD];   // 12672B
    __shared__ int nid_sh[2][CHUNK];

    // cooperative load of col (lid+64) weights
    for (int t = tid; t < EDGE_DIM * 64; t += 128) {
        int k = t >> 6, col = t & 63;
        WshB[t] = Wn[(size_t)(col + 64) * wstride + woff + k];
    }

    const int cpb = (nck + gridDim.x - 1) / gridDim.x;
    const int c0b = blockIdx.x * cpb;
    const int c1b = min(c0b + cpb, nck);
    if (c0b >= c1b) return;

    // staging slots: l = tid, tid+128, tid+256 (<352); l = e*11+kk bijection
    const int e0_ = tid / 11,          kk0 = tid % 11;
    const int e1_ = (tid + 128) / 11,  kk1 = (tid + 128) % 11;
    const int e2_ = (tid + 256) / 11,  kk2 = (tid + 256) % 11;
    const bool has2 = (tid + 256) < 352;

    {   // prologue: stage chunk c0b into buffer 0
        size_t base = (size_t)c0b * CHUNK;
        float4 v0 = *reinterpret_cast<const float4*>(g_eaP + (base + e0_) * EDGE_PAD + 4 * kk0);
        float4 v1 = *reinterpret_cast<const float4*>(g_eaP + (base + e1_) * EDGE_PAD + 4 * kk1);
        float4 v2 = has2 ? *reinterpret_cast<const float4*>(g_eaP + (base + e2_) * EDGE_PAD + 4 * kk2)
                         : make_float4(0.f, 0.f, 0.f, 0.f);
        float* b = ea[0];
        b[(4*kk0+0)*KPAD + e0_] = v0.x; b[(4*kk0+1)*KPAD + e0_] = v0.y;
        b[(4*kk0+2)*KPAD + e0_] = v0.z; b[(4*kk0+3)*KPAD + e0_] = v0.w;
        b[(4*kk1+0)*KPAD + e1_] = v1.x; b[(4*kk1+1)*KPAD + e1_] = v1.y;
        b[(4*kk1+2)*KPAD + e1_] = v1.z; b[(4*kk1+3)*KPAD + e1_] = v1.w;
        if (has2) {
            b[(4*kk2+0)*KPAD + e2_] = v2.x; b[(4*kk2+1)*KPAD + e2_] = v2.y;
            b[(4*kk2+2)*KPAD + e2_] = v2.z; b[(4*kk2+3)*KPAD + e2_] = v2.w;
        }
        if (tid < CHUNK) nid_sh[0][tid] = g_nid[base + tid];
    }
    __syncthreads();   // covers staging AND WshB fill

    int   cur = -1;
    float av0 = 0.0f, av1 = 0.0f;
    float np0 = 0.0f, np1 = 0.0f;

    for (int c = c0b; c < c1b; c++) {
        const int bi = (c - c0b) & 1;      // local parity (prologue filled buf 0)
        const bool more = (c + 1) < c1b;

        float4 v0, v1, v2;
        int nxt_nid = 0;
        if (more) {
            size_t base = (size_t)(c + 1) * CHUNK;
            v0 = *reinterpret_cast<const float4*>(g_eaP + (base + e0_) * EDGE_PAD + 4 * kk0);
            v1 = *reinterpret_cast<const float4*>(g_eaP + (base + e1_) * EDGE_PAD + 4 * kk1);
            if (has2)
                v2 = *reinterpret_cast<const float4*>(g_eaP + (base + e2_) * EDGE_PAD + 4 * kk2);
            if (tid < CHUNK) nxt_nid = g_nid[base + tid];
        }

        const float* buf = ea[bi];
        #pragma unroll 1
        for (int sub = 0; sub < 2; sub++) {
            // this thread's 8 edges this sub: [ebase + sub*8, +8)
            unsigned long long aA0 = 0, aA1 = 0, aA2 = 0, aA3 = 0;
            unsigned long long aB0 = 0, aB1 = 0, aB2 = 0, aB3 = 0;
            const float* bp = buf + ebase + sub * 8;
            #pragma unroll
            for (int k = 0; k < EDGE_DIM; k++) {
                ulonglong2 p01 = *reinterpret_cast<const ulonglong2*>(bp + k * KPAD);
                ulonglong2 p23 = *reinterpret_cast<const ulonglong2*>(bp + k * KPAD + 4);
                unsigned long long wA = pack2(Wa[k], Wa[k]);
                float wb = WshB[k * 64 + lid];
                unsigned long long wB = pack2(wb, wb);
                FMA2(aA0, wA, p01.x); FMA2(aA1, wA, p01.y);
                FMA2(aA2, wA, p23.x); FMA2(aA3, wA, p23.y);
                FMA2(aB0, wB, p01.x); FMA2(aB1, wB, p01.y);
                FMA2(aB2, wB, p23.x); FMA2(aB3, wB, p23.y);
            }
            float fA[8], fB[8];
            unpack2(aA0, fA[0], fA[1]); unpack2(aA1, fA[2], fA[3]);
            unpack2(aA2, fA[4], fA[5]); unpack2(aA3, fA[6], fA[7]);
            unpack2(aB0, fB[0], fB[1]); unpack2(aB1, fB[2], fB[3]);
            unpack2(aB2, fB[4], fB[5]); unpack2(aB3, fB[6], fB[7]);
            #pragma unroll
            for (int p = 0; p < 8; p++) {
                int nid = nid_sh[bi][ebase + sub * 8 + p];
                if (nid != cur) {
                    float n0 = g_np[(size_t)nid * HDIM + c0];
                    float n1 = g_np[(size_t)nid * HDIM + c1];
                    if (cur >= 0) {
                        atomicAdd(&hout[(size_t)cur * HDIM + c0], av0);
                        atomicAdd(&hout[(size_t)cur * HDIM + c1], av1);
                    }
                    cur = nid; av0 = 0.0f; av1 = 0.0f; np0 = n0; np1 = n1;
                }
                av0 += tanh_mufu(np0 + fA[p]);
                av1 += tanh_mufu(np1 + fB[p]);
            }
        }
        __syncthreads();

        if (more) {
            float* b = ea[bi ^ 1];
            b[(4*kk0+0)*KPAD + e0_] = v0.x; b[(4*kk0+1)*KPAD + e0_] = v0.y;
            b[(4*kk0+2)*KPAD + e0_] = v0.z; b[(4*kk0+3)*KPAD + e0_] = v0.w;
            b[(4*kk1+0)*KPAD + e1_] = v1.x; b[(4*kk1+1)*KPAD + e1_] = v1.y;
            b[(4*kk1+2)*KPAD + e1_] = v1.z; b[(4*kk1+3)*KPAD + e1_] = v1.w;
            if (has2) {
                b[(4*kk2+0)*KPAD + e2_] = v2.x; b[(4*kk2+1)*KPAD + e2_] = v2.y;
                b[(4*kk2+2)*KPAD + e2_] = v2.z; b[(4*kk2+3)*KPAD + e2_] = v2.w;
            }
            if (tid < CHUNK) nid_sh[bi ^ 1][tid] = nxt_nid;
            __syncthreads();
        }
    }
    if (cur >= 0) {
        atomicAdd(&hout[(size_t)cur * HDIM + c0], av0);
        atomicAdd(&hout[(size_t)cur * HDIM + c1], av1);
    }
}

// gate MLP: 128->64->32->1
__global__ __launch_bounds__(128) void k_gate(
    const float* __restrict__ h,
    const float* __restrict__ Wg1, const float* __restrict__ bg1,
    const float* __restrict__ Wg2, const float* __restrict__ bg2,
    const float* __restrict__ Wg3, const float* __restrict__ bg3)
{
    __shared__ float W1s[128 * 64];
    __shared__ float W2s[64 * 32];
    __shared__ float W3s[32];
    __shared__ float b1s[64], b2s[32];
    __shared__ float h_sh[128 * 2];
    __shared__ float g1s[64 * 2];
    int tid = threadIdx.x;

    for (int t = tid; t < 128 * 64; t += 128) {
        int j = t / 128, k = t % 128;
        W1s[k * 64 + j] = Wg1[j * 128 + k];
    }
    for (int t = tid; t < 64 * 32; t += 128) {
        int j = t / 64, k = t % 64;
        W2s[k * 32 + j] = Wg2[j * 64 + k];
    }
    if (tid < 32) W3s[tid] = Wg3[tid];
    if (tid < 64) b1s[tid] = bg1[tid];
    if (tid < 32) b2s[tid] = bg2[tid];
    __syncthreads();

    int npairs = (N_NODES + 1) / 2;
    for (int p = blockIdx.x; p < npairs; p += gridDim.x) {
        for (int t = tid; t < 256; t += 128) {
            int node = t / 128, k = t % 128;
            int n = 2 * p + node;
            h_sh[k * 2 + node] = (n < N_NODES) ? h[(size_t)n * HDIM + k] : 0.0f;
        }
        __syncthreads();
        int j = tid & 63, half = tid >> 6;
        float a = 0;
        #pragma unroll 4
        for (int k = 0; k < 128; k++) a += W1s[k * 64 + j] * h_sh[k * 2 + half];
        g1s[j * 2 + half] = fmaxf(a + b1s[j], 0.0f);
        __syncthreads();
        if (j < 32) {
            float a2 = 0;
            #pragma unroll 4
            for (int k = 0; k < 64; k++) a2 += W2s[k * 32 + j] * g1s[k * 2 + half];
            float g2 = fmaxf(a2 + b2s[j], 0.0f);
            float v = g2 * W3s[j];
            for (int o = 16; o > 0; o >>= 1) v += __shfl_down_sync(0xffffffffu, v, o);
            int n = 2 * p + half;
            if (j == 0 && n < N_NODES) g_gate[n] = v + bg3[0];
        }
        __syncthreads();
    }
}

__global__ void k_gstats() {
    int n = blockIdx.x * blockDim.x + threadIdx.x;
    if (n < N_NODES) {
        int b = g_batch[n];
        atomicMax(&g_gmax[b], enc_f(g_gate[n]));
        atomicMin(&g_glo[b], n);
        atomicMax(&g_ghi[b], n);
    }
}

__global__ void k_gsum() {
    int n = blockIdx.x * blockDim.x + threadIdx.x;
    if (n < N_NODES) {
        int b = g_batch[n];
        atomicAdd(&g_gsum[b], __expf(g_gate[n] - dec_f(g_gmax[b])));
    }
}

__global__ void k_att(float* __restrict__ att) {
    int n = blockIdx.x * blockDim.x + threadIdx.x;
    if (n < N_NODES) {
        int b = g_batch[n];
        float g = __expf(g_gate[n] - dec_f(g_gmax[b]));
        att[n] = g / (g_gsum[b] + 1e-16f);
    }
}

__global__ void k_emb(const float* __restrict__ h, const float* __restrict__ att) {
    int b = blockIdx.x, q = blockIdx.y, j = threadIdx.x;
    int lo = g_glo[b], hi = g_ghi[b];
    if (hi < lo) return;
    int len = hi - lo + 1;
    int per = (len + 3) / 4;
    int s = lo + q * per;
    int e = min(s + per, hi + 1);
    if (s >= e) return;
    float acc = 0.0f;
    for (int n = s; n < e; n++)
        acc += att[n] * h[(size_t)n * HDIM + j];
    atomicAdd(&g_emb[b * HDIM + j], acc);
}

__global__ __launch_bounds__(256) void k_final(
    const float* __restrict__ us, const float* __restrict__ ud,
    const float* __restrict__ Wl1, const float* __restrict__ bl1,
    const float* __restrict__ Wl2, const float* __restrict__ bl2,
    const float* __restrict__ Wl3, const float* __restrict__ bl3,
    const float* __restrict__ Wl,  const float* __restrict__ bl,
    float* __restrict__ outp)
{
    __shared__ float e2[256], o1[256], o2[128], o3[64], o4[4];
    int b = blockIdx.x, t = threadIdx.x;
    if (t < 128)       e2[t] = g_emb[b * 128 + t];
    else if (t < 192)  e2[t] = us[b * 64 + (t - 128)];
    else               e2[t] = ud[b * 64 + (t - 192)];
    __syncthreads();
    float a = 0;
    for (int k = 0; k < 256; k++) a += Wl1[t * 256 + k] * e2[k];
    o1[t] = fmaxf(a + bl1[t], 0.0f);
    __syncthreads();
    if (t < 128) {
        a = 0;
        for (int k = 0; k < 256; k++) a += Wl2[t * 256 + k] * o1[k];
        o2[t] = fmaxf(a + bl2[t], 0.0f);
    }
    __syncthreads();
    if (t < 64) {
        a = 0;
        for (int k = 0; k < 128; k++) a += Wl3[t * 128 + k] * o2[k];
        o3[t] = fmaxf(a + bl3[t], 0.0f);
    }
    __syncthreads();
    if (t < 4) {
        a = 0;
        for (int k = 0; k < 64; k++) a += Wl[t * 64 + k] * o3[k];
        o4[t] = a + bl[t];
    }
    __syncthreads();
    if (t == 0) {
        float s = o4[0] + o4[1] + o4[2] + o4[3];
        outp[b * 5 + 0] = o4[0];
        outp[b * 5 + 1] = o4[1];
        outp[b * 5 + 2] = o4[2];
        outp[b * 5 + 3] = o4[3];
        outp[b * 5 + 4] = s;
    }
}

// ------------------------- launch -------------------------------------------
extern "C" void kernel_launch(void* const* d_in, const int* in_sizes, int n_in,
                              void* d_out, int out_size)
{
    const float* x    = (const float*)d_in[0];
    const float* ea   = (const float*)d_in[1];
    const float* us   = (const float*)d_in[2];
    const float* ud   = (const float*)d_in[3];
    const float* W1n  = (const float*)d_in[4];
    const float* b1n  = (const float*)d_in[5];
    const float* W1r  = (const float*)d_in[6];
    const float* b1r  = (const float*)d_in[7];
    const float* W2n  = (const float*)d_in[8];
    const float* b2n  = (const float*)d_in[9];
    const float* W2r  = (const float*)d_in[10];
    const float* b2r  = (const float*)d_in[11];
    const float* W3n  = (const float*)d_in[12];
    const float* b3n  = (const float*)d_in[13];
    const float* W3r  = (const float*)d_in[14];
    const float* b3r  = (const float*)d_in[15];
    const float* Wg1  = (const float*)d_in[16];
    const float* bg1  = (const float*)d_in[17];
    const float* Wg2  = (const float*)d_in[18];
    const float* bg2  = (const float*)d_in[19];
    const float* Wg3  = (const float*)d_in[20];
    const float* bg3  = (const float*)d_in[21];
    const float* Wl1  = (const float*)d_in[22];
    const float* bl1  = (const float*)d_in[23];
    const float* Wl2  = (const float*)d_in[24];
    const float* bl2  = (const float*)d_in[25];
    const float* Wl3  = (const float*)d_in[26];
    const float* bl3  = (const float*)d_in[27];
    const float* Wl   = (const float*)d_in[28];
    const float* bl   = (const float*)d_in[29];
    const int* ei32   = (const int*)d_in[30];
    const int* b32    = (const int*)d_in[31];

    float* outp = (float*)d_out;
    float* att  = outp + N_GRAPHS * 5;

    cudaFuncSetAttribute(k_np,
                         cudaFuncAttributeMaxDynamicSharedMemorySize, 100000);
    cudaFuncSetAttribute(k_root,
                         cudaFuncAttributeMaxDynamicSharedMemorySize, 100000);

    int smemN35  = (IN_DIM * HDIM + IN_DIM * 4 + HDIM) * sizeof(float);
    int smemN128 = (HDIM * HDIM + HDIM * 4 + HDIM) * sizeof(float);

    k_detect<<<1, 32>>>(ei32, b32);                      // launch 1
    k_init<<<256, 256>>>();                              // launch 2
    k_hist<<<(N_EDGES + 255) / 256, 256>>>(ei32);        // launch 3

    // PROFILING PROBE (launch 4 == ncu slot): new k_agg on 9.5% chunk subset
    // into g_hB (fully overwritten by layer-2 k_root before any read).
    k_agg<<<1184, 128>>>(W1n, IN_DIM + EDGE_DIM, IN_DIM, g_hB, 4736);

    k_batchload<<<(N_NODES + 255) / 256, 256>>>(b32);
    k_scan<<<1, SCAN_T>>>();
    k_scatter<<<(N_EDGES + 255) / 256, 256>>>();
    k_permute<<<2048, 256>>>(ea);

    // layer 1: x(35) -> hA
    k_np<<<1184, 128, smemN35>>>(x, IN_DIM, W1n, IN_DIM + EDGE_DIM, b1n);
    k_root<<<1184, 128, smemN35>>>(x, IN_DIM, W1r, b1r, g_hA);
    k_agg<<<1184, 128>>>(W1n, IN_DIM + EDGE_DIM, IN_DIM, g_hA, N_CHUNKS);
    // layer 2: hA(128) -> hB
    k_np<<<1184, 128, smemN128>>>(g_hA, HDIM, W2n, HDIM + EDGE_DIM, b2n);
    k_root<<<1184, 128, smemN128>>>(g_hA, HDIM, W2r, b2r, g_hB);
    k_agg<<<1184, 128>>>(W2n, HDIM + EDGE_DIM, HDIM, g_hB, N_CHUNKS);
    // layer 3: hB(128) -> hA
    k_np<<<1184, 128, smemN128>>>(g_hB, HDIM, W3n, HDIM + EDGE_DIM, b3n);
    k_root<<<1184, 128, smemN128>>>(g_hB, HDIM, W3r, b3r, g_hA);
    k_agg<<<1184, 128>>>(W3n, HDIM + EDGE_DIM, HDIM, g_hA, N_CHUNKS);

    // readout
    k_gate<<<1184, 128>>>(g_hA, Wg1, bg1, Wg2, bg2, Wg3, bg3);
    k_gstats<<<(N_NODES + 255) / 256, 256>>>();
    k_gsum<<<(N_NODES + 255) / 256, 256>>>();
    k_att<<<(N_NODES + 255) / 256, 256>>>(att);
    k_emb<<<dim3(N_GRAPHS, 4), HDIM>>>(g_hA, att);
    k_final<<<N_GRAPHS, 256>>>(us, ud, Wl1, bl1, Wl2, bl2, Wl3, bl3, Wl, bl, outp);
}